// round 1
// baseline (speedup 1.0000x reference)
#include <cuda_runtime.h>

#define BPB     8
#define THREADS 128   // 8 groups of 16 lanes (13 active per group)

// Output layout: concat of recon[B,4,13,13], mu[B,13,16], logvar[B,13,16] (fp32)
#define R_MU 22151168ull
#define R_LV 28966912ull

__device__ __forceinline__ float leaky(float v) {
    return v >= 0.f ? v : 0.01f * v;
}

__global__ __launch_bounds__(THREADS) void vae_fused(
    const float* __restrict__ adj,
    const float* __restrict__ init_weight,
    const float* __restrict__ eps_param,
    const float* __restrict__ mlp_w0,
    const float* __restrict__ mlp_b0,
    const float* __restrict__ mlp_w1,
    const float* __restrict__ mlp_b1,
    const float* __restrict__ bn_in_gamma,
    const float* __restrict__ bn_in_beta,
    const float* __restrict__ bn_in_mean,
    const float* __restrict__ bn_in_var,
    const float* __restrict__ bn_out_gamma,
    const float* __restrict__ bn_out_beta,
    const float* __restrict__ bn_out_mean,
    const float* __restrict__ bn_out_var,
    const float* __restrict__ fc1_w,
    const float* __restrict__ fc1_b,
    const float* __restrict__ fc2_w,
    const float* __restrict__ fc2_b,
    const float* __restrict__ dec_w,
    const float* __restrict__ dec_b,
    float* __restrict__ out)
{
    // ---- shared parameter staging (per block, read by all 8 groups) ----
    __shared__ float winit_s[208];                 // [m*16+d]
    __shared__ float eps1p_s[4];
    __shared__ float w0_s[1024], b0_s[64];         // [l*256 + e*16 + d], [l*16+e]
    __shared__ float w1_s[1024], b1_s[64];
    __shared__ float bnis_s[52], bnit_s[52];       // [l*13+n] scale/shift (in)
    __shared__ float bnos_s[52], bnot_s[52];       // (out)
    __shared__ float fc1w_s[256], fc1b_s[16];
    __shared__ float fc2w_s[256], fc2b_s[16];
    __shared__ float decw_s[1024], decb_s[64];     // [k*256 + d*16 + j], [k*16+d]
    __shared__ float adj_s[BPB * 676];             // per-b: [i*169 + n*13 + m]
    __shared__ float xs_s[BPB * 221];              // per-b: [n*17 + d] (pitch 17 -> conflict-free)

    const int tid = threadIdx.x;

    for (int i = tid; i < 208; i += THREADS) winit_s[i] = init_weight[i];
    if (tid < 4) eps1p_s[tid] = 1.f + eps_param[tid];
    for (int i = tid; i < 1024; i += THREADS) {
        w0_s[i] = mlp_w0[i]; w1_s[i] = mlp_w1[i]; decw_s[i] = dec_w[i];
    }
    for (int i = tid; i < 64; i += THREADS) {
        b0_s[i] = mlp_b0[i]; b1_s[i] = mlp_b1[i]; decb_s[i] = dec_b[i];
    }
    for (int i = tid; i < 52; i += THREADS) {
        float s = bn_in_gamma[i] * rsqrtf(bn_in_var[i] + 1e-5f);
        bnis_s[i] = s;
        bnit_s[i] = bn_in_beta[i] - bn_in_mean[i] * s;
        float so = bn_out_gamma[i] * rsqrtf(bn_out_var[i] + 1e-5f);
        bnos_s[i] = so;
        bnot_s[i] = bn_out_beta[i] - bn_out_mean[i] * so;
    }
    for (int i = tid; i < 256; i += THREADS) { fc1w_s[i] = fc1_w[i]; fc2w_s[i] = fc2_w[i]; }
    if (tid < 16) { fc1b_s[tid] = fc1_b[tid]; fc2b_s[tid] = fc2_b[tid]; }

    // adj for this block's 8 batch elements (contiguous, float4)
    {
        const float4* src = (const float4*)(adj + (size_t)blockIdx.x * (BPB * 676));
        float4* dst = (float4*)adj_s;
        for (int i = tid; i < BPB * 169; i += THREADS) dst[i] = src[i];
    }
    __syncthreads();

    // ---- per-group setup ----
    const int grp = tid >> 4;          // 0..7
    const int n   = tid & 15;          // node id; lanes 13..15 idle
    const int b   = blockIdx.x * BPB + grp;
    const float* adjb = adj_s + grp * 676;
    float*       xs   = xs_s  + grp * 221;
    const bool act = (n < 13);

    float x[16];

    // ---- init: x[n,d] = sum_{i,m} adj[i,n,m] * W[m,d]  (W indep of i -> sum adj over i first)
    if (act) {
        float asum[13];
#pragma unroll
        for (int m = 0; m < 13; m++)
            asum[m] = adjb[n*13+m] + adjb[169 + n*13+m] + adjb[338 + n*13+m] + adjb[507 + n*13+m];
#pragma unroll
        for (int d = 0; d < 16; d++) x[d] = 0.f;
#pragma unroll
        for (int m = 0; m < 13; m++) {
            float a = asum[m];
#pragma unroll
            for (int d = 0; d < 16; d++) x[d] += a * winit_s[m*16 + d];
        }
#pragma unroll
        for (int d = 0; d < 16; d++) xs[n*17 + d] = x[d];
    }
    __syncwarp();

    // ---- 4 GIN layers ----
#pragma unroll 1
    for (int l = 0; l < 4; l++) {
        if (act) {
            const float ep = eps1p_s[l];
            float agg[16];
#pragma unroll
            for (int d = 0; d < 16; d++) agg[d] = ep * x[d];
            // neighbor[n, i*4+g] = sum_m adj[i,n,m] * x_old[m, i*4+g]
#pragma unroll
            for (int i = 0; i < 4; i++) {
#pragma unroll
                for (int m = 0; m < 13; m++) {
                    float a = adjb[i*169 + n*13 + m];
#pragma unroll
                    for (int g = 0; g < 4; g++)
                        agg[i*4 + g] += a * xs[m*17 + i*4 + g];
                }
            }
            const float* w0 = w0_s + l*256;
            const float* b0 = b0_s + l*16;
            const float si = bnis_s[l*13 + n], ti = bnit_s[l*13 + n];
            float h1[16];
#pragma unroll
            for (int e = 0; e < 16; e++) {
                float acc = b0[e];
#pragma unroll
                for (int d = 0; d < 16; d++) acc += agg[d] * w0[e*16 + d];
                h1[e] = leaky(si * acc + ti);
            }
            const float* w1 = w1_s + l*256;
            const float* b1 = b1_s + l*16;
            const float so = bnos_s[l*13 + n], to = bnot_s[l*13 + n];
#pragma unroll
            for (int e = 0; e < 16; e++) {
                float acc = b1[e];
#pragma unroll
                for (int d = 0; d < 16; d++) acc += h1[d] * w1[e*16 + d];
                x[e] = leaky(so * acc + to);
            }
        }
        __syncwarp();   // all reads of old xs done
        if (act) {
#pragma unroll
            for (int d = 0; d < 16; d++) xs[n*17 + d] = x[d];
        }
        __syncwarp();   // new xs visible
    }

    // ---- heads: mu / logvar ----
    float mu[16];
    if (act) {
        float lv[16];
#pragma unroll
        for (int e = 0; e < 16; e++) {
            float a1 = fc1b_s[e], a2 = fc2b_s[e];
#pragma unroll
            for (int d = 0; d < 16; d++) {
                a1 += x[d] * fc1w_s[e*16 + d];
                a2 += x[d] * fc2w_s[e*16 + d];
            }
            mu[e] = a1; lv[e] = a2;
        }
        const size_t moff = ((size_t)b * 13 + n) * 16;
        float4* mo = (float4*)(out + R_MU + moff);
        float4* lo = (float4*)(out + R_LV + moff);
#pragma unroll
        for (int q = 0; q < 4; q++) {
            mo[q] = make_float4(mu[q*4+0], mu[q*4+1], mu[q*4+2], mu[q*4+3]);
            lo[q] = make_float4(lv[q*4+0], lv[q*4+1], lv[q*4+2], lv[q*4+3]);
        }
    }

    // ---- decoder: per k, temp[n,d] = mu[n,:]·dec_w[k,d,:] + dec_b[k,d]; recon = relu(temp temp^T)
#pragma unroll 1
    for (int k = 0; k < 4; k++) {
        __syncwarp();   // previous k's recon reads of xs done
        float t[16];
        if (act) {
            const float* dw = decw_s + k*256;
#pragma unroll
            for (int d = 0; d < 16; d++) {
                float acc = decb_s[k*16 + d];
#pragma unroll
                for (int j = 0; j < 16; j++) acc += mu[j] * dw[d*16 + j];
                t[d] = acc;
                xs[n*17 + d] = acc;     // publish row for other nodes
            }
        }
        __syncwarp();
        if (act) {
            float* ro = out + (size_t)b * 676 + k * 169 + n * 13;
#pragma unroll
            for (int m = 0; m < 13; m++) {
                float acc = 0.f;
#pragma unroll
                for (int d = 0; d < 16; d++) acc += t[d] * xs[m*17 + d];
                ro[m] = acc > 0.f ? acc : 0.f;
            }
        }
    }
}

extern "C" void kernel_launch(void* const* d_in, const int* in_sizes, int n_in,
                              void* d_out, int out_size) {
    (void)in_sizes; (void)n_in; (void)out_size;
    vae_fused<<<32768 / BPB, THREADS>>>(
        (const float*)d_in[0],  (const float*)d_in[1],  (const float*)d_in[2],
        (const float*)d_in[3],  (const float*)d_in[4],  (const float*)d_in[5],
        (const float*)d_in[6],  (const float*)d_in[7],  (const float*)d_in[8],
        (const float*)d_in[9],  (const float*)d_in[10], (const float*)d_in[11],
        (const float*)d_in[12], (const float*)d_in[13], (const float*)d_in[14],
        (const float*)d_in[15], (const float*)d_in[16], (const float*)d_in[17],
        (const float*)d_in[18], (const float*)d_in[19], (const float*)d_in[20],
        (float*)d_out);
}

// round 2
// speedup vs baseline: 1.2817x; 1.2817x over previous
#include <cuda_runtime.h>

#define BPB     8
#define THREADS 128   // 8 groups of 16 lanes (13 active per group)

// Output layout: concat of recon[B,4,13,13], mu[B,13,16], logvar[B,13,16] (fp32)
#define R_MU 22151168ull
#define R_LV 28966912ull

typedef unsigned long long u64;

__device__ __forceinline__ void ffma2(u64 &d, u64 a, u64 b) {
    asm("fma.rn.f32x2 %0, %1, %2, %0;" : "+l"(d) : "l"(a), "l"(b));
}
__device__ __forceinline__ u64 pack2(float lo, float hi) {
    u64 r; asm("mov.b64 %0, {%1, %2};" : "=l"(r) : "f"(lo), "f"(hi)); return r;
}
__device__ __forceinline__ float2 unpack2(u64 v) {
    float2 r; asm("mov.b64 {%0, %1}, %2;" : "=f"(r.x), "=f"(r.y) : "l"(v)); return r;
}
__device__ __forceinline__ float leaky(float v) { return v >= 0.f ? v : 0.01f * v; }

// dot(a[0..15], w_row[0..15]) with a pre-packed as 8 f32x2 pairs, w as 4 float4
__device__ __forceinline__ float dot16(const float4* __restrict__ wrow, const u64* a2) {
    u64 acc = 0ull;  // (0.f, 0.f)
#pragma unroll
    for (int q = 0; q < 4; q++) {
        float4 w = wrow[q];
        ffma2(acc, a2[2*q],     pack2(w.x, w.y));
        ffma2(acc, a2[2*q + 1], pack2(w.z, w.w));
    }
    float2 f = unpack2(acc);
    return f.x + f.y;
}

__global__ __launch_bounds__(THREADS, 4) void vae_fused(
    const float* __restrict__ adj,
    const float* __restrict__ init_weight,
    const float* __restrict__ eps_param,
    const float* __restrict__ mlp_w0,
    const float* __restrict__ mlp_b0,
    const float* __restrict__ mlp_w1,
    const float* __restrict__ mlp_b1,
    const float* __restrict__ bn_in_gamma,
    const float* __restrict__ bn_in_beta,
    const float* __restrict__ bn_in_mean,
    const float* __restrict__ bn_in_var,
    const float* __restrict__ bn_out_gamma,
    const float* __restrict__ bn_out_beta,
    const float* __restrict__ bn_out_mean,
    const float* __restrict__ bn_out_var,
    const float* __restrict__ fc1_w,
    const float* __restrict__ fc1_b,
    const float* __restrict__ fc2_w,
    const float* __restrict__ fc2_b,
    const float* __restrict__ dec_w,
    const float* __restrict__ dec_b,
    float* __restrict__ out)
{
    // ---- shared parameter staging (float4 layouts for LDS.128) ----
    __shared__ float4 winitv[52];                  // init_weight [m][d] rows
    __shared__ float  eps1p_s[4];
    __shared__ float4 w0v[256], w1v[256], decv[256];   // [l|k][e|d][4xfloat4]
    __shared__ float4 fc1v[64], fc2v[64];
    __shared__ float  b0_s[64], b1_s[64], decb_s[64], fc1b_s[16], fc2b_s[16];
    __shared__ float  bnis_s[52], bnit_s[52], bnos_s[52], bnot_s[52];
    __shared__ float  adj_s[BPB * 676];            // per-b: [i*169 + n*13 + m]
    __shared__ float4 xsv[BPB * 65];               // per-b: row n at [n*5 + q], q=0..3

    const int tid = threadIdx.x;

    for (int i = tid; i < 52; i += THREADS) winitv[i] = ((const float4*)init_weight)[i];
    if (tid < 4) eps1p_s[tid] = 1.f + eps_param[tid];
    for (int i = tid; i < 256; i += THREADS) {
        w0v[i]  = ((const float4*)mlp_w0)[i];
        w1v[i]  = ((const float4*)mlp_w1)[i];
        decv[i] = ((const float4*)dec_w)[i];
    }
    for (int i = tid; i < 64; i += THREADS) {
        b0_s[i] = mlp_b0[i]; b1_s[i] = mlp_b1[i]; decb_s[i] = dec_b[i];
        fc1v[i] = ((const float4*)fc1_w)[i];
        fc2v[i] = ((const float4*)fc2_w)[i];
    }
    for (int i = tid; i < 52; i += THREADS) {
        float s = bn_in_gamma[i] * rsqrtf(bn_in_var[i] + 1e-5f);
        bnis_s[i] = s;
        bnit_s[i] = bn_in_beta[i] - bn_in_mean[i] * s;
        float so = bn_out_gamma[i] * rsqrtf(bn_out_var[i] + 1e-5f);
        bnos_s[i] = so;
        bnot_s[i] = bn_out_beta[i] - bn_out_mean[i] * so;
    }
    if (tid < 16) { fc1b_s[tid] = fc1_b[tid]; fc2b_s[tid] = fc2_b[tid]; }

    {   // adj for this block's 8 batch elements (contiguous, float4)
        const float4* src = (const float4*)(adj + (size_t)blockIdx.x * (BPB * 676));
        float4* dst = (float4*)adj_s;
        for (int i = tid; i < BPB * 169; i += THREADS) dst[i] = src[i];
    }
    __syncthreads();

    // ---- per-group setup ----
    const int grp = tid >> 4;
    const int n   = tid & 15;
    const int b   = blockIdx.x * BPB + grp;
    const float* adjb = adj_s + grp * 676;
    float4*      xs4  = xsv   + grp * 65;
    const bool act = (n < 13);

    float x[16];

    // ---- init: x[n,:] = sum_m (sum_i adj[i,n,m]) * W[m,:]
    if (act) {
        float asum[13];
#pragma unroll
        for (int m = 0; m < 13; m++)
            asum[m] = adjb[n*13+m] + adjb[169 + n*13+m] + adjb[338 + n*13+m] + adjb[507 + n*13+m];
        u64 x2[8];
#pragma unroll
        for (int q = 0; q < 8; q++) x2[q] = 0ull;
#pragma unroll
        for (int m = 0; m < 13; m++) {
            u64 a = pack2(asum[m], asum[m]);
            const float4* wr = winitv + m * 4;
#pragma unroll
            for (int q = 0; q < 4; q++) {
                float4 w = wr[q];
                ffma2(x2[2*q],     a, pack2(w.x, w.y));
                ffma2(x2[2*q + 1], a, pack2(w.z, w.w));
            }
        }
#pragma unroll
        for (int q = 0; q < 8; q++) { float2 f = unpack2(x2[q]); x[2*q] = f.x; x[2*q+1] = f.y; }
#pragma unroll
        for (int q = 0; q < 4; q++)
            xs4[n*5 + q] = make_float4(x[4*q], x[4*q+1], x[4*q+2], x[4*q+3]);
    }
    __syncwarp();

    // ---- 4 GIN layers ----
#pragma unroll 1
    for (int l = 0; l < 4; l++) {
        if (act) {
            const float ep = eps1p_s[l];
            u64 agg2[8];
#pragma unroll
            for (int q = 0; q < 8; q++) agg2[q] = pack2(ep * x[2*q], ep * x[2*q+1]);
            // neighbor[n, i*4+g] = sum_m adj[i,n,m] * x_old[m, i*4+g]
#pragma unroll
            for (int i = 0; i < 4; i++) {
                const float* arow = adjb + i*169 + n*13;
#pragma unroll
                for (int m = 0; m < 13; m++) {
                    float av = arow[m];
                    u64 a = pack2(av, av);
                    float4 xr = xs4[m*5 + i];
                    ffma2(agg2[2*i],     a, pack2(xr.x, xr.y));
                    ffma2(agg2[2*i + 1], a, pack2(xr.z, xr.w));
                }
            }
            const float si = bnis_s[l*13 + n], ti = bnit_s[l*13 + n];
            const float* bb0 = b0_s + l*16;
            const float4* w0base = w0v + l*64;
            float h1[16];
#pragma unroll
            for (int e = 0; e < 16; e++) {
                float s = dot16(w0base + e*4, agg2) + bb0[e];
                h1[e] = leaky(si * s + ti);
            }
            u64 h2[8];
#pragma unroll
            for (int q = 0; q < 8; q++) h2[q] = pack2(h1[2*q], h1[2*q+1]);
            const float so = bnos_s[l*13 + n], to = bnot_s[l*13 + n];
            const float* bb1 = b1_s + l*16;
            const float4* w1base = w1v + l*64;
#pragma unroll
            for (int e = 0; e < 16; e++) {
                float s = dot16(w1base + e*4, h2) + bb1[e];
                x[e] = leaky(so * s + to);
            }
        }
        __syncwarp();   // all reads of old xs done
        if (act) {
#pragma unroll
            for (int q = 0; q < 4; q++)
                xs4[n*5 + q] = make_float4(x[4*q], x[4*q+1], x[4*q+2], x[4*q+3]);
        }
        __syncwarp();   // new xs visible
    }

    // ---- heads: mu / logvar ----
    float mu[16];
    if (act) {
        u64 x2[8];
#pragma unroll
        for (int q = 0; q < 8; q++) x2[q] = pack2(x[2*q], x[2*q+1]);
        float lv[16];
#pragma unroll
        for (int e = 0; e < 16; e++) {
            mu[e] = dot16(fc1v + e*4, x2) + fc1b_s[e];
            lv[e] = dot16(fc2v + e*4, x2) + fc2b_s[e];
        }
        const size_t moff = ((size_t)b * 13 + n) * 16;
        float4* mo = (float4*)(out + R_MU + moff);
        float4* lo = (float4*)(out + R_LV + moff);
#pragma unroll
        for (int q = 0; q < 4; q++) {
            mo[q] = make_float4(mu[4*q], mu[4*q+1], mu[4*q+2], mu[4*q+3]);
            lo[q] = make_float4(lv[4*q], lv[4*q+1], lv[4*q+2], lv[4*q+3]);
        }
    }

    // ---- decoder ----
    u64 mu2[8];
    if (act) {
#pragma unroll
        for (int q = 0; q < 8; q++) mu2[q] = pack2(mu[2*q], mu[2*q+1]);
    }
#pragma unroll 1
    for (int k = 0; k < 4; k++) {
        __syncwarp();   // previous k's recon reads of xs done
        float t[16];
        if (act) {
            const float4* dwb = decv + k*64;
            const float*  dbb = decb_s + k*16;
#pragma unroll
            for (int d = 0; d < 16; d++)
                t[d] = dot16(dwb + d*4, mu2) + dbb[d];
#pragma unroll
            for (int q = 0; q < 4; q++)
                xs4[n*5 + q] = make_float4(t[4*q], t[4*q+1], t[4*q+2], t[4*q+3]);
        }
        __syncwarp();
        if (act) {
            u64 t2[8];
#pragma unroll
            for (int q = 0; q < 8; q++) t2[q] = pack2(t[2*q], t[2*q+1]);
            float* ro = out + (size_t)b * 676 + k * 169 + n * 13;
#pragma unroll
            for (int m = 0; m < 13; m++) {
                u64 acc = 0ull;
#pragma unroll
                for (int q = 0; q < 4; q++) {
                    float4 xr = xs4[m*5 + q];
                    ffma2(acc, t2[2*q],     pack2(xr.x, xr.y));
                    ffma2(acc, t2[2*q + 1], pack2(xr.z, xr.w));
                }
                float2 f = unpack2(acc);
                float s = f.x + f.y;
                ro[m] = s > 0.f ? s : 0.f;
            }
        }
    }
}

extern "C" void kernel_launch(void* const* d_in, const int* in_sizes, int n_in,
                              void* d_out, int out_size) {
    (void)in_sizes; (void)n_in; (void)out_size;
    vae_fused<<<32768 / BPB, THREADS>>>(
        (const float*)d_in[0],  (const float*)d_in[1],  (const float*)d_in[2],
        (const float*)d_in[3],  (const float*)d_in[4],  (const float*)d_in[5],
        (const float*)d_in[6],  (const float*)d_in[7],  (const float*)d_in[8],
        (const float*)d_in[9],  (const float*)d_in[10], (const float*)d_in[11],
        (const float*)d_in[12], (const float*)d_in[13], (const float*)d_in[14],
        (const float*)d_in[15], (const float*)d_in[16], (const float*)d_in[17],
        (const float*)d_in[18], (const float*)d_in[19], (const float*)d_in[20],
        (float*)d_out);
}

// round 3
// speedup vs baseline: 1.3435x; 1.0482x over previous
#include <cuda_runtime.h>

#define THREADS 128
#define GPB 16            // graphs per block (8 lane-groups x 2 graphs/thread)

// Output layout: concat of recon[B,4,13,13], mu[B,13,16], logvar[B,13,16] (fp32)
#define R_MU 22151168ull
#define R_LV 28966912ull

typedef unsigned long long u64;

__device__ __forceinline__ void ffma2(u64 &d, u64 a, u64 b) {
    asm("fma.rn.f32x2 %0, %1, %2, %0;" : "+l"(d) : "l"(a), "l"(b));
}
__device__ __forceinline__ u64 pack2(float lo, float hi) {
    u64 r; asm("mov.b64 %0, {%1, %2};" : "=l"(r) : "f"(lo), "f"(hi)); return r;
}
__device__ __forceinline__ float2 unpack2(u64 v) {
    float2 r; asm("mov.b64 {%0, %1}, %2;" : "=f"(r.x), "=f"(r.y) : "l"(v)); return r;
}
__device__ __forceinline__ float leaky(float v) { return v >= 0.f ? v : 0.01f * v; }
__device__ __forceinline__ u64 plo(float4 w) { return pack2(w.x, w.y); }
__device__ __forceinline__ u64 phi(float4 w) { return pack2(w.z, w.w); }

struct __align__(16) Smem {
    float4 winitv[52];                    // init_weight rows
    float4 w0v[256], w1v[256], decv[256]; // [l|k][e|d][4]
    float4 fc1v[64], fc2v[64];
    float4 xsv[GPB * 65];                 // per-graph node rows, pitch 5 float4
    float  adj[GPB * 676];                // per-graph [i*169 + n*13 + m]; reused as recon staging
    float  eps1p[4];
    float  b0[64], b1[64], decb[64], fc1b[16], fc2b[16];
    float  bnis[52], bnit[52], bnos[52], bnot[52];
};

__global__ __launch_bounds__(THREADS, 2) void vae_fused(
    const float* __restrict__ adj,
    const float* __restrict__ init_weight,
    const float* __restrict__ eps_param,
    const float* __restrict__ mlp_w0,  const float* __restrict__ mlp_b0,
    const float* __restrict__ mlp_w1,  const float* __restrict__ mlp_b1,
    const float* __restrict__ bn_in_gamma,  const float* __restrict__ bn_in_beta,
    const float* __restrict__ bn_in_mean,   const float* __restrict__ bn_in_var,
    const float* __restrict__ bn_out_gamma, const float* __restrict__ bn_out_beta,
    const float* __restrict__ bn_out_mean,  const float* __restrict__ bn_out_var,
    const float* __restrict__ fc1_w, const float* __restrict__ fc1_b,
    const float* __restrict__ fc2_w, const float* __restrict__ fc2_b,
    const float* __restrict__ dec_w, const float* __restrict__ dec_b,
    float* __restrict__ out)
{
    extern __shared__ Smem sm[];
    Smem& s = sm[0];
    const int tid = threadIdx.x;

    for (int i = tid; i < 52; i += THREADS) s.winitv[i] = ((const float4*)init_weight)[i];
    if (tid < 4) s.eps1p[tid] = 1.f + eps_param[tid];
    for (int i = tid; i < 256; i += THREADS) {
        s.w0v[i]  = ((const float4*)mlp_w0)[i];
        s.w1v[i]  = ((const float4*)mlp_w1)[i];
        s.decv[i] = ((const float4*)dec_w)[i];
    }
    for (int i = tid; i < 64; i += THREADS) {
        s.b0[i] = mlp_b0[i]; s.b1[i] = mlp_b1[i]; s.decb[i] = dec_b[i];
        s.fc1v[i] = ((const float4*)fc1_w)[i];
        s.fc2v[i] = ((const float4*)fc2_w)[i];
    }
    for (int i = tid; i < 52; i += THREADS) {
        float sc = bn_in_gamma[i] * rsqrtf(bn_in_var[i] + 1e-5f);
        s.bnis[i] = sc;
        s.bnit[i] = bn_in_beta[i] - bn_in_mean[i] * sc;
        float so = bn_out_gamma[i] * rsqrtf(bn_out_var[i] + 1e-5f);
        s.bnos[i] = so;
        s.bnot[i] = bn_out_beta[i] - bn_out_mean[i] * so;
    }
    if (tid < 16) { s.fc1b[tid] = fc1_b[tid]; s.fc2b[tid] = fc2_b[tid]; }

    {   // adj for this block's 16 graphs (contiguous float4)
        const float4* src = (const float4*)(adj + (size_t)blockIdx.x * (GPB * 676));
        float4* dst = (float4*)s.adj;
        for (int i = tid; i < GPB * 169; i += THREADS) dst[i] = src[i];
    }
    __syncthreads();

    const int grp = tid >> 4;          // 0..7
    const int n   = tid & 15;          // node; lanes 13..15 idle for compute
    const int g0  = grp * 2;           // local graph ids g0, g0+1
    const size_t b0g = (size_t)blockIdx.x * GPB + g0;
    const float* ad[2] = { s.adj + g0 * 676, s.adj + (g0 + 1) * 676 };
    float4*      xp[2] = { s.xsv + g0 * 65,  s.xsv + (g0 + 1) * 65 };
    const bool act = (n < 13);

    float x[2][16];

    // ---- init: x[n,:] = sum_m (sum_i adj[i,n,m]) * W[m,:]
    if (act) {
        float as[2][13];
#pragma unroll
        for (int g = 0; g < 2; g++)
#pragma unroll
            for (int m = 0; m < 13; m++)
                as[g][m] = ad[g][n*13+m] + ad[g][169+n*13+m] + ad[g][338+n*13+m] + ad[g][507+n*13+m];
        u64 x2[2][8];
#pragma unroll
        for (int g = 0; g < 2; g++)
#pragma unroll
            for (int q = 0; q < 8; q++) x2[g][q] = 0ull;
#pragma unroll
        for (int m = 0; m < 13; m++) {
            const float4* wr = s.winitv + m * 4;
            float4 w0_ = wr[0], w1_ = wr[1], w2_ = wr[2], w3_ = wr[3];
            u64 pw[8] = { plo(w0_), phi(w0_), plo(w1_), phi(w1_),
                          plo(w2_), phi(w2_), plo(w3_), phi(w3_) };
#pragma unroll
            for (int g = 0; g < 2; g++) {
                u64 a = pack2(as[g][m], as[g][m]);
#pragma unroll
                for (int q = 0; q < 8; q++) ffma2(x2[g][q], a, pw[q]);
            }
        }
#pragma unroll
        for (int g = 0; g < 2; g++) {
#pragma unroll
            for (int q = 0; q < 8; q++) { float2 f = unpack2(x2[g][q]); x[g][2*q] = f.x; x[g][2*q+1] = f.y; }
#pragma unroll
            for (int q = 0; q < 4; q++)
                xp[g][n*5 + q] = make_float4(x[g][4*q], x[g][4*q+1], x[g][4*q+2], x[g][4*q+3]);
        }
    }
    __syncwarp();

    // ---- 4 GIN layers ----
#pragma unroll 1
    for (int l = 0; l < 4; l++) {
        if (act) {
            const float ep = s.eps1p[l];
            u64 agg2[2][8];
#pragma unroll
            for (int g = 0; g < 2; g++)
#pragma unroll
                for (int q = 0; q < 8; q++) agg2[g][q] = pack2(ep * x[g][2*q], ep * x[g][2*q+1]);
#pragma unroll
            for (int i = 0; i < 4; i++) {
#pragma unroll
                for (int m = 0; m < 13; m++) {
#pragma unroll
                    for (int g = 0; g < 2; g++) {
                        float av = ad[g][i*169 + n*13 + m];
                        u64 a = pack2(av, av);
                        float4 xr = xp[g][m*5 + i];
                        ffma2(agg2[g][2*i],     a, plo(xr));
                        ffma2(agg2[g][2*i + 1], a, phi(xr));
                    }
                }
            }
            const float si = s.bnis[l*13 + n], ti = s.bnit[l*13 + n];
            const float so = s.bnos[l*13 + n], to = s.bnot[l*13 + n];
            const float4* w0b = s.w0v + l*64;
            const float*  bb0 = s.b0 + l*16;
            float h1[2][16];
#pragma unroll
            for (int e = 0; e < 16; e++) {
                const float4* wr = w0b + e*4;
                float4 wa = wr[0], wb = wr[1], wc = wr[2], wd = wr[3];
                u64 pw[8] = { plo(wa), phi(wa), plo(wb), phi(wb),
                              plo(wc), phi(wc), plo(wd), phi(wd) };
#pragma unroll
                for (int g = 0; g < 2; g++) {
                    u64 acc = 0ull;
#pragma unroll
                    for (int q = 0; q < 8; q++) ffma2(acc, agg2[g][q], pw[q]);
                    float2 f = unpack2(acc);
                    h1[g][e] = leaky(si * (f.x + f.y + bb0[e]) + ti);
                }
            }
            u64 h2[2][8];
#pragma unroll
            for (int g = 0; g < 2; g++)
#pragma unroll
                for (int q = 0; q < 8; q++) h2[g][q] = pack2(h1[g][2*q], h1[g][2*q+1]);
            const float4* w1b = s.w1v + l*64;
            const float*  bb1 = s.b1 + l*16;
#pragma unroll
            for (int e = 0; e < 16; e++) {
                const float4* wr = w1b + e*4;
                float4 wa = wr[0], wb = wr[1], wc = wr[2], wd = wr[3];
                u64 pw[8] = { plo(wa), phi(wa), plo(wb), phi(wb),
                              plo(wc), phi(wc), plo(wd), phi(wd) };
#pragma unroll
                for (int g = 0; g < 2; g++) {
                    u64 acc = 0ull;
#pragma unroll
                    for (int q = 0; q < 8; q++) ffma2(acc, h2[g][q], pw[q]);
                    float2 f = unpack2(acc);
                    x[g][e] = leaky(so * (f.x + f.y + bb1[e]) + to);
                }
            }
        }
        __syncwarp();
        if (act) {
#pragma unroll
            for (int g = 0; g < 2; g++)
#pragma unroll
                for (int q = 0; q < 4; q++)
                    xp[g][n*5 + q] = make_float4(x[g][4*q], x[g][4*q+1], x[g][4*q+2], x[g][4*q+3]);
        }
        __syncwarp();
    }

    // ---- heads: mu / logvar ----
    float mu[2][16];
    {
        float lv[2][16];
        if (act) {
            u64 x2[2][8];
#pragma unroll
            for (int g = 0; g < 2; g++)
#pragma unroll
                for (int q = 0; q < 8; q++) x2[g][q] = pack2(x[g][2*q], x[g][2*q+1]);
#pragma unroll
            for (int e = 0; e < 16; e++) {
                const float4* r1 = s.fc1v + e*4;
                const float4* r2 = s.fc2v + e*4;
                float4 a1 = r1[0], b1_ = r1[1], c1 = r1[2], d1 = r1[3];
                float4 a2 = r2[0], b2_ = r2[1], c2 = r2[2], d2 = r2[3];
                u64 p1[8] = { plo(a1), phi(a1), plo(b1_), phi(b1_), plo(c1), phi(c1), plo(d1), phi(d1) };
                u64 p2[8] = { plo(a2), phi(a2), plo(b2_), phi(b2_), plo(c2), phi(c2), plo(d2), phi(d2) };
#pragma unroll
                for (int g = 0; g < 2; g++) {
                    u64 acc1 = 0ull, acc2 = 0ull;
#pragma unroll
                    for (int q = 0; q < 8; q++) { ffma2(acc1, x2[g][q], p1[q]); ffma2(acc2, x2[g][q], p2[q]); }
                    float2 f1 = unpack2(acc1), f2 = unpack2(acc2);
                    mu[g][e] = f1.x + f1.y + s.fc1b[e];
                    lv[g][e] = f2.x + f2.y + s.fc2b[e];
                }
            }
        }
        // stage + coalesced write: logvar then mu (xs buffer reused)
        __syncwarp();
        if (act) {
#pragma unroll
            for (int g = 0; g < 2; g++)
#pragma unroll
                for (int q = 0; q < 4; q++)
                    xp[g][n*5 + q] = make_float4(lv[g][4*q], lv[g][4*q+1], lv[g][4*q+2], lv[g][4*q+3]);
        }
        __syncwarp();
#pragma unroll
        for (int g = 0; g < 2; g++) {
            float4* o4 = (float4*)(out + R_LV + (b0g + g) * 208);
#pragma unroll
            for (int it = 0; it < 4; it++) {
                int idx = it * 16 + n;            // 0..63, need 0..51
                if (idx < 52) o4[idx] = xp[g][(idx >> 2) * 5 + (idx & 3)];
            }
        }
        __syncwarp();
        if (act) {
#pragma unroll
            for (int g = 0; g < 2; g++)
#pragma unroll
                for (int q = 0; q < 4; q++)
                    xp[g][n*5 + q] = make_float4(mu[g][4*q], mu[g][4*q+1], mu[g][4*q+2], mu[g][4*q+3]);
        }
        __syncwarp();
#pragma unroll
        for (int g = 0; g < 2; g++) {
            float4* o4 = (float4*)(out + R_MU + (b0g + g) * 208);
#pragma unroll
            for (int it = 0; it < 4; it++) {
                int idx = it * 16 + n;
                if (idx < 52) o4[idx] = xp[g][(idx >> 2) * 5 + (idx & 3)];
            }
        }
    }

    // ---- decoder: recon staged into the (dead) adj slice, then coalesced out ----
    u64 mu2[2][8];
    if (act) {
#pragma unroll
        for (int g = 0; g < 2; g++)
#pragma unroll
            for (int q = 0; q < 8; q++) mu2[g][q] = pack2(mu[g][2*q], mu[g][2*q+1]);
    }
    float* rec[2] = { (float*)ad[0], (float*)ad[1] };   // 676 floats per graph

#pragma unroll 1
    for (int k = 0; k < 4; k++) {
        __syncwarp();
        float t[2][16];
        if (act) {
            const float4* dwb = s.decv + k*64;
            const float*  dbb = s.decb + k*16;
#pragma unroll
            for (int d = 0; d < 16; d++) {
                const float4* wr = dwb + d*4;
                float4 wa = wr[0], wb = wr[1], wc = wr[2], wd = wr[3];
                u64 pw[8] = { plo(wa), phi(wa), plo(wb), phi(wb),
                              plo(wc), phi(wc), plo(wd), phi(wd) };
#pragma unroll
                for (int g = 0; g < 2; g++) {
                    u64 acc = 0ull;
#pragma unroll
                    for (int q = 0; q < 8; q++) ffma2(acc, mu2[g][q], pw[q]);
                    float2 f = unpack2(acc);
                    t[g][d] = f.x + f.y + dbb[d];
                }
            }
#pragma unroll
            for (int g = 0; g < 2; g++)
#pragma unroll
                for (int q = 0; q < 4; q++)
                    xp[g][n*5 + q] = make_float4(t[g][4*q], t[g][4*q+1], t[g][4*q+2], t[g][4*q+3]);
        }
        __syncwarp();
        if (act) {
#pragma unroll
            for (int g = 0; g < 2; g++) {
                u64 t2[8];
#pragma unroll
                for (int q = 0; q < 8; q++) t2[q] = pack2(t[g][2*q], t[g][2*q+1]);
                float* rr = rec[g] + k * 169 + n * 13;
#pragma unroll
                for (int m = 0; m < 13; m++) {
                    u64 acc = 0ull;
#pragma unroll
                    for (int q = 0; q < 4; q++) {
                        float4 xr = xp[g][m*5 + q];
                        ffma2(acc, t2[2*q],     plo(xr));
                        ffma2(acc, t2[2*q + 1], phi(xr));
                    }
                    float2 f = unpack2(acc);
                    float sv = f.x + f.y;
                    rr[m] = sv > 0.f ? sv : 0.f;   // stage to SMEM (stride-13 -> conflict-free)
                }
            }
        }
    }
    __syncwarp();
    // coalesced recon writeout: 676 floats = 169 float4 per graph
#pragma unroll
    for (int g = 0; g < 2; g++) {
        const float4* r4 = (const float4*)rec[g];
        float4* o4 = (float4*)(out + (b0g + g) * 676);
#pragma unroll
        for (int it = 0; it < 11; it++) {
            int idx = it * 16 + n;               // 0..175, need 0..168
            if (idx < 169) o4[idx] = r4[idx];
        }
    }
}

extern "C" void kernel_launch(void* const* d_in, const int* in_sizes, int n_in,
                              void* d_out, int out_size) {
    (void)in_sizes; (void)n_in; (void)out_size;
    cudaFuncSetAttribute(vae_fused, cudaFuncAttributeMaxDynamicSharedMemorySize,
                         (int)sizeof(Smem));
    vae_fused<<<32768 / GPB, THREADS, sizeof(Smem)>>>(
        (const float*)d_in[0],  (const float*)d_in[1],  (const float*)d_in[2],
        (const float*)d_in[3],  (const float*)d_in[4],  (const float*)d_in[5],
        (const float*)d_in[6],  (const float*)d_in[7],  (const float*)d_in[8],
        (const float*)d_in[9],  (const float*)d_in[10], (const float*)d_in[11],
        (const float*)d_in[12], (const float*)d_in[13], (const float*)d_in[14],
        (const float*)d_in[15], (const float*)d_in[16], (const float*)d_in[17],
        (const float*)d_in[18], (const float*)d_in[19], (const float*)d_in[20],
        (float*)d_out);
}

// round 4
// speedup vs baseline: 1.4553x; 1.0831x over previous
#include <cuda_runtime.h>

#define THREADS 128
#define GPB 16            // graphs per block (8 lane-groups x 2 graphs/thread)

// Output layout: concat of recon[B,4,13,13], mu[B,13,16], logvar[B,13,16] (fp32)
#define R_MU 22151168ull
#define R_LV 28966912ull

typedef unsigned long long u64;

__device__ __forceinline__ void ffma2(u64 &d, u64 a, u64 b) {
    asm("fma.rn.f32x2 %0, %1, %2, %0;" : "+l"(d) : "l"(a), "l"(b));
}
__device__ __forceinline__ u64 pack2(float lo, float hi) {
    u64 r; asm("mov.b64 %0, {%1, %2};" : "=l"(r) : "f"(lo), "f"(hi)); return r;
}
__device__ __forceinline__ float2 unpack2(u64 v) {
    float2 r; asm("mov.b64 {%0, %1}, %2;" : "=f"(r.x), "=f"(r.y) : "l"(v)); return r;
}
__device__ __forceinline__ float leaky(float v) { return v >= 0.f ? v : 0.01f * v; }
__device__ __forceinline__ u64 plo(float4 w) { return pack2(w.x, w.y); }
__device__ __forceinline__ u64 phi(float4 w) { return pack2(w.z, w.w); }

// 16-wide dot with 2 accumulator chains (depth 4 each)
__device__ __forceinline__ float dot16s(const u64* pw, const u64* a2) {
    u64 accA = 0ull, accB = 0ull;
#pragma unroll
    for (int q = 0; q < 4; q++) ffma2(accA, a2[q],     pw[q]);
#pragma unroll
    for (int q = 0; q < 4; q++) ffma2(accB, a2[q + 4], pw[q + 4]);
    float2 fa = unpack2(accA), fb = unpack2(accB);
    return (fa.x + fb.x) + (fa.y + fb.y);
}

struct __align__(16) Smem {
    float4 winitv[52];                    // init_weight rows
    float4 w0v[256], w1v[256], decv[256]; // [l|k][e|d][4]
    float4 fc1v[64], fc2v[64];
    float4 xsv[GPB * 65];                 // per-graph node rows, pitch 5 float4
    float  adj[GPB * 676];                // per-graph [i*169 + n*13 + m]; reused as recon staging
    float  eps1p[4];
    float  b0[64], b1[64], decb[64], fc1b[16], fc2b[16];
};

__global__ __launch_bounds__(THREADS, 3) void vae_fused(
    const float* __restrict__ adj,
    const float* __restrict__ init_weight,
    const float* __restrict__ eps_param,
    const float* __restrict__ mlp_w0,  const float* __restrict__ mlp_b0,
    const float* __restrict__ mlp_w1,  const float* __restrict__ mlp_b1,
    const float* __restrict__ bn_in_gamma,  const float* __restrict__ bn_in_beta,
    const float* __restrict__ bn_in_mean,   const float* __restrict__ bn_in_var,
    const float* __restrict__ bn_out_gamma, const float* __restrict__ bn_out_beta,
    const float* __restrict__ bn_out_mean,  const float* __restrict__ bn_out_var,
    const float* __restrict__ fc1_w, const float* __restrict__ fc1_b,
    const float* __restrict__ fc2_w, const float* __restrict__ fc2_b,
    const float* __restrict__ dec_w, const float* __restrict__ dec_b,
    float* __restrict__ out)
{
    extern __shared__ Smem sm[];
    Smem& s = sm[0];
    const int tid = threadIdx.x;

    for (int i = tid; i < 52; i += THREADS) s.winitv[i] = ((const float4*)init_weight)[i];
    if (tid < 4) s.eps1p[tid] = 1.f + eps_param[tid];
    for (int i = tid; i < 256; i += THREADS) {
        s.w0v[i]  = ((const float4*)mlp_w0)[i];
        s.w1v[i]  = ((const float4*)mlp_w1)[i];
        s.decv[i] = ((const float4*)dec_w)[i];
    }
    for (int i = tid; i < 64; i += THREADS) {
        s.b0[i] = mlp_b0[i]; s.b1[i] = mlp_b1[i]; s.decb[i] = dec_b[i];
        s.fc1v[i] = ((const float4*)fc1_w)[i];
        s.fc2v[i] = ((const float4*)fc2_w)[i];
    }
    if (tid < 16) { s.fc1b[tid] = fc1_b[tid]; s.fc2b[tid] = fc2_b[tid]; }

    {   // adj for this block's 16 graphs (contiguous float4)
        const float4* src = (const float4*)(adj + (size_t)blockIdx.x * (GPB * 676));
        float4* dst = (float4*)s.adj;
        for (int i = tid; i < GPB * 169; i += THREADS) dst[i] = src[i];
    }
    __syncthreads();

    const int grp = tid >> 4;          // 0..7
    const int n   = tid & 15;          // node; lanes 13..15 idle for compute
    const int g0  = grp * 2;           // local graph ids g0, g0+1
    const size_t b0g = (size_t)blockIdx.x * GPB + g0;
    const float* ad[2] = { s.adj + g0 * 676, s.adj + (g0 + 1) * 676 };
    float4*      xp[2] = { s.xsv + g0 * 65,  s.xsv + (g0 + 1) * 65 };
    const bool act = (n < 13);
    const int nn = act ? n : 0;        // clamp for safe param loads

    float x[2][16];

    // ---- init: x[n,:] = sum_m (sum_i adj[i,n,m]) * W[m,:]
    if (act) {
        float as[2][13];
#pragma unroll
        for (int g = 0; g < 2; g++)
#pragma unroll
            for (int m = 0; m < 13; m++)
                as[g][m] = ad[g][n*13+m] + ad[g][169+n*13+m] + ad[g][338+n*13+m] + ad[g][507+n*13+m];
        u64 x2[2][8];
#pragma unroll
        for (int g = 0; g < 2; g++)
#pragma unroll
            for (int q = 0; q < 8; q++) x2[g][q] = 0ull;
#pragma unroll
        for (int m = 0; m < 13; m++) {
            const float4* wr = s.winitv + m * 4;
            float4 w0_ = wr[0], w1_ = wr[1], w2_ = wr[2], w3_ = wr[3];
            u64 pw[8] = { plo(w0_), phi(w0_), plo(w1_), phi(w1_),
                          plo(w2_), phi(w2_), plo(w3_), phi(w3_) };
#pragma unroll
            for (int g = 0; g < 2; g++) {
                u64 a = pack2(as[g][m], as[g][m]);
#pragma unroll
                for (int q = 0; q < 8; q++) ffma2(x2[g][q], a, pw[q]);
            }
        }
#pragma unroll
        for (int g = 0; g < 2; g++) {
#pragma unroll
            for (int q = 0; q < 8; q++) { float2 f = unpack2(x2[g][q]); x[g][2*q] = f.x; x[g][2*q+1] = f.y; }
#pragma unroll
            for (int q = 0; q < 4; q++)
                xp[g][n*5 + q] = make_float4(x[g][4*q], x[g][4*q+1], x[g][4*q+2], x[g][4*q+3]);
        }
    }
    __syncwarp();

    // ---- 4 GIN layers ----
#pragma unroll 1
    for (int l = 0; l < 4; l++) {
        // BN affine params from global (L1/L2-cached, tiny)
        const int pi = l * 13 + nn;
        const float si = bn_in_gamma[pi]  * rsqrtf(bn_in_var[pi]  + 1e-5f);
        const float ti = bn_in_beta[pi]   - bn_in_mean[pi]  * si;
        const float so = bn_out_gamma[pi] * rsqrtf(bn_out_var[pi] + 1e-5f);
        const float to = bn_out_beta[pi]  - bn_out_mean[pi] * so;
        if (act) {
            const float ep = s.eps1p[l];
            u64 agg2[2][8];
#pragma unroll
            for (int g = 0; g < 2; g++)
#pragma unroll
                for (int q = 0; q < 8; q++) agg2[g][q] = pack2(ep * x[g][2*q], ep * x[g][2*q+1]);
#pragma unroll
            for (int i = 0; i < 4; i++) {
#pragma unroll
                for (int m = 0; m < 13; m++) {
#pragma unroll
                    for (int g = 0; g < 2; g++) {
                        float av = ad[g][i*169 + n*13 + m];
                        u64 a = pack2(av, av);
                        float4 xr = xp[g][m*5 + i];
                        ffma2(agg2[g][2*i],     a, plo(xr));
                        ffma2(agg2[g][2*i + 1], a, phi(xr));
                    }
                }
            }
            const float4* w0b = s.w0v + l*64;
            const float*  bb0 = s.b0 + l*16;
            float h1[2][16];
#pragma unroll
            for (int e = 0; e < 16; e++) {
                const float4* wr = w0b + e*4;
                float4 wa = wr[0], wb = wr[1], wc = wr[2], wd = wr[3];
                u64 pw[8] = { plo(wa), phi(wa), plo(wb), phi(wb),
                              plo(wc), phi(wc), plo(wd), phi(wd) };
#pragma unroll
                for (int g = 0; g < 2; g++)
                    h1[g][e] = leaky(si * (dot16s(pw, agg2[g]) + bb0[e]) + ti);
            }
            u64 h2[2][8];
#pragma unroll
            for (int g = 0; g < 2; g++)
#pragma unroll
                for (int q = 0; q < 8; q++) h2[g][q] = pack2(h1[g][2*q], h1[g][2*q+1]);
            const float4* w1b = s.w1v + l*64;
            const float*  bb1 = s.b1 + l*16;
#pragma unroll
            for (int e = 0; e < 16; e++) {
                const float4* wr = w1b + e*4;
                float4 wa = wr[0], wb = wr[1], wc = wr[2], wd = wr[3];
                u64 pw[8] = { plo(wa), phi(wa), plo(wb), phi(wb),
                              plo(wc), phi(wc), plo(wd), phi(wd) };
#pragma unroll
                for (int g = 0; g < 2; g++)
                    x[g][e] = leaky(so * (dot16s(pw, h2[g]) + bb1[e]) + to);
            }
        }
        __syncwarp();
        if (act) {
#pragma unroll
            for (int g = 0; g < 2; g++)
#pragma unroll
                for (int q = 0; q < 4; q++)
                    xp[g][n*5 + q] = make_float4(x[g][4*q], x[g][4*q+1], x[g][4*q+2], x[g][4*q+3]);
        }
        __syncwarp();
    }

    // ---- heads: mu / logvar ----
    float mu[2][16];
    {
        float lv[2][16];
        if (act) {
            u64 x2[2][8];
#pragma unroll
            for (int g = 0; g < 2; g++)
#pragma unroll
                for (int q = 0; q < 8; q++) x2[g][q] = pack2(x[g][2*q], x[g][2*q+1]);
#pragma unroll
            for (int e = 0; e < 16; e++) {
                const float4* r1 = s.fc1v + e*4;
                const float4* r2 = s.fc2v + e*4;
                float4 a1 = r1[0], b1_ = r1[1], c1 = r1[2], d1 = r1[3];
                float4 a2 = r2[0], b2_ = r2[1], c2 = r2[2], d2 = r2[3];
                u64 p1[8] = { plo(a1), phi(a1), plo(b1_), phi(b1_), plo(c1), phi(c1), plo(d1), phi(d1) };
                u64 p2[8] = { plo(a2), phi(a2), plo(b2_), phi(b2_), plo(c2), phi(c2), plo(d2), phi(d2) };
#pragma unroll
                for (int g = 0; g < 2; g++) {
                    mu[g][e] = dot16s(p1, x2[g]) + s.fc1b[e];
                    lv[g][e] = dot16s(p2, x2[g]) + s.fc2b[e];
                }
            }
        }
        // stage + coalesced write: logvar then mu (xs buffer reused)
        __syncwarp();
        if (act) {
#pragma unroll
            for (int g = 0; g < 2; g++)
#pragma unroll
                for (int q = 0; q < 4; q++)
                    xp[g][n*5 + q] = make_float4(lv[g][4*q], lv[g][4*q+1], lv[g][4*q+2], lv[g][4*q+3]);
        }
        __syncwarp();
#pragma unroll
        for (int g = 0; g < 2; g++) {
            float4* o4 = (float4*)(out + R_LV + (b0g + g) * 208);
#pragma unroll
            for (int it = 0; it < 4; it++) {
                int idx = it * 16 + n;            // 0..63, need 0..51
                if (idx < 52) o4[idx] = xp[g][(idx >> 2) * 5 + (idx & 3)];
            }
        }
        __syncwarp();
        if (act) {
#pragma unroll
            for (int g = 0; g < 2; g++)
#pragma unroll
                for (int q = 0; q < 4; q++)
                    xp[g][n*5 + q] = make_float4(mu[g][4*q], mu[g][4*q+1], mu[g][4*q+2], mu[g][4*q+3]);
        }
        __syncwarp();
#pragma unroll
        for (int g = 0; g < 2; g++) {
            float4* o4 = (float4*)(out + R_MU + (b0g + g) * 208);
#pragma unroll
            for (int it = 0; it < 4; it++) {
                int idx = it * 16 + n;
                if (idx < 52) o4[idx] = xp[g][(idx >> 2) * 5 + (idx & 3)];
            }
        }
    }

    // ---- decoder: recon staged into the (dead) adj slice, then coalesced out ----
    u64 mu2[2][8];
    if (act) {
#pragma unroll
        for (int g = 0; g < 2; g++)
#pragma unroll
            for (int q = 0; q < 8; q++) mu2[g][q] = pack2(mu[g][2*q], mu[g][2*q+1]);
    }
    float* rec[2] = { (float*)ad[0], (float*)ad[1] };   // 676 floats per graph

#pragma unroll 1
    for (int k = 0; k < 4; k++) {
        __syncwarp();
        float t[2][16];
        if (act) {
            const float4* dwb = s.decv + k*64;
            const float*  dbb = s.decb + k*16;
#pragma unroll
            for (int d = 0; d < 16; d++) {
                const float4* wr = dwb + d*4;
                float4 wa = wr[0], wb = wr[1], wc = wr[2], wd = wr[3];
                u64 pw[8] = { plo(wa), phi(wa), plo(wb), phi(wb),
                              plo(wc), phi(wc), plo(wd), phi(wd) };
#pragma unroll
                for (int g = 0; g < 2; g++)
                    t[g][d] = dot16s(pw, mu2[g]) + dbb[d];
            }
#pragma unroll
            for (int g = 0; g < 2; g++)
#pragma unroll
                for (int q = 0; q < 4; q++)
                    xp[g][n*5 + q] = make_float4(t[g][4*q], t[g][4*q+1], t[g][4*q+2], t[g][4*q+3]);
        }
        __syncwarp();
        if (act) {
#pragma unroll
            for (int g = 0; g < 2; g++) {
                u64 t2[8];
#pragma unroll
                for (int q = 0; q < 8; q++) t2[q] = pack2(t[g][2*q], t[g][2*q+1]);
                float* rr = rec[g] + k * 169 + n * 13;
#pragma unroll
                for (int m = 0; m < 13; m++) {
                    u64 accA = 0ull, accB = 0ull;
#pragma unroll
                    for (int q = 0; q < 2; q++) {
                        float4 xr = xp[g][m*5 + q];
                        ffma2(accA, t2[2*q],     plo(xr));
                        ffma2(accA, t2[2*q + 1], phi(xr));
                    }
#pragma unroll
                    for (int q = 2; q < 4; q++) {
                        float4 xr = xp[g][m*5 + q];
                        ffma2(accB, t2[2*q],     plo(xr));
                        ffma2(accB, t2[2*q + 1], phi(xr));
                    }
                    float2 fa = unpack2(accA), fb = unpack2(accB);
                    float sv = (fa.x + fb.x) + (fa.y + fb.y);
                    rr[m] = sv > 0.f ? sv : 0.f;   // stage to SMEM
                }
            }
        }
    }
    __syncwarp();
    // coalesced recon writeout: 676 floats = 169 float4 per graph
#pragma unroll
    for (int g = 0; g < 2; g++) {
        const float4* r4 = (const float4*)rec[g];
        float4* o4 = (float4*)(out + (b0g + g) * 676);
#pragma unroll
        for (int it = 0; it < 11; it++) {
            int idx = it * 16 + n;               // 0..175, need 0..168
            if (idx < 169) o4[idx] = r4[idx];
        }
    }
}

extern "C" void kernel_launch(void* const* d_in, const int* in_sizes, int n_in,
                              void* d_out, int out_size) {
    (void)in_sizes; (void)n_in; (void)out_size;
    cudaFuncSetAttribute(vae_fused, cudaFuncAttributeMaxDynamicSharedMemorySize,
                         (int)sizeof(Smem));
    vae_fused<<<32768 / GPB, THREADS, sizeof(Smem)>>>(
        (const float*)d_in[0],  (const float*)d_in[1],  (const float*)d_in[2],
        (const float*)d_in[3],  (const float*)d_in[4],  (const float*)d_in[5],
        (const float*)d_in[6],  (const float*)d_in[7],  (const float*)d_in[8],
        (const float*)d_in[9],  (const float*)d_in[10], (const float*)d_in[11],
        (const float*)d_in[12], (const float*)d_in[13], (const float*)d_in[14],
        (const float*)d_in[15], (const float*)d_in[16], (const float*)d_in[17],
        (const float*)d_in[18], (const float*)d_in[19], (const float*)d_in[20],
        (float*)d_out);
}